// round 2
// baseline (speedup 1.0000x reference)
#include <cuda_runtime.h>
#include <cuda_bf16.h>
#include <cstdint>

#define N_NODES 50000
#define D_FEAT  128
#define N_EDGES 600000

// scratch (no cudaMalloc allowed)
__device__ float g_counts[N_NODES];
__device__ int   g_is64;   // 1 if index arrays are int64, 0 if int32

// ---------------------------------------------------------------------------
// Kernel 0: detect index dtype. Deterministic pure function of input bytes.
// int64 data (values < 2^31) read as int32 pairs => (val, 0, val, 0, ...).
// ---------------------------------------------------------------------------
__global__ void detect_kernel(const int* __restrict__ idx_as_i32) {
    if (threadIdx.x == 0 && blockIdx.x == 0) {
        int is64 = 1;
        #pragma unroll 1
        for (int i = 0; i < 256; i++) {
            int lo = idx_as_i32[2 * i];
            int hi = idx_as_i32[2 * i + 1];
            if (hi != 0 || lo < 0 || lo >= N_NODES) { is64 = 0; break; }
        }
        g_is64 = is64;
    }
}

// ---------------------------------------------------------------------------
// Kernel 1: zero output and counts
// ---------------------------------------------------------------------------
__global__ void init_kernel(float* __restrict__ out) {
    int i = blockIdx.x * blockDim.x + threadIdx.x;
    int total = N_NODES * (D_FEAT / 4);
    if (i < total) {
        ((float4*)out)[i] = make_float4(0.f, 0.f, 0.f, 0.f);
    }
    if (i < N_NODES) {
        g_counts[i] = 0.f;
    }
}

// ---------------------------------------------------------------------------
// Kernel 2: one warp per edge. Each lane moves one float4 (32*4 = 128 floats).
// Gather source row (L2-resident), vector-RED onto destination row.
// ---------------------------------------------------------------------------
__global__ void scatter_kernel(const float* __restrict__ emb,
                               const void* __restrict__ src_raw,
                               const void* __restrict__ dst_raw,
                               float* __restrict__ out) {
    int gtid = blockIdx.x * blockDim.x + threadIdx.x;
    int edge = gtid >> 5;
    int lane = gtid & 31;
    if (edge >= N_EDGES) return;

    int is64 = g_is64;  // L2/const-cached, negligible
    long long s, d;
    if (is64) {
        s = __ldg((const long long*)src_raw + edge);
        d = __ldg((const long long*)dst_raw + edge);
    } else {
        s = __ldg((const int*)src_raw + edge);
        d = __ldg((const int*)dst_raw + edge);
    }
    // defensive clamp: never fault even if detection were wrong
    if (s < 0 || s >= N_NODES || d < 0 || d >= N_NODES) return;

    const float4 v = __ldg((const float4*)(emb + s * (long long)D_FEAT) + lane);
    float4* o = (float4*)(out + d * (long long)D_FEAT) + lane;

    asm volatile("red.global.add.v4.f32 [%0], {%1, %2, %3, %4};"
                 :: "l"(o), "f"(v.x), "f"(v.y), "f"(v.z), "f"(v.w)
                 : "memory");

    if (lane == 0) {
        atomicAdd(&g_counts[(int)d], 1.0f);
    }
}

// ---------------------------------------------------------------------------
// Kernel 3: scale each row by 1/max(count,1). Zero-in-degree rows stay 0.
// ---------------------------------------------------------------------------
__global__ void finalize_kernel(float* __restrict__ out) {
    int i = blockIdx.x * blockDim.x + threadIdx.x;
    int total = N_NODES * (D_FEAT / 4);
    if (i >= total) return;

    int node = i >> 5;  // 32 float4 per node
    float c = g_counts[node];
    float inv = (c > 0.f) ? (1.0f / c) : 0.0f;

    float4 v = ((float4*)out)[i];
    v.x *= inv; v.y *= inv; v.z *= inv; v.w *= inv;
    ((float4*)out)[i] = v;
}

// ---------------------------------------------------------------------------
extern "C" void kernel_launch(void* const* d_in, const int* in_sizes, int n_in,
                              void* d_out, int out_size) {
    const float* emb = (const float*)d_in[0];
    const void*  src = d_in[1];
    const void*  dst = d_in[2];
    float* out = (float*)d_out;

    detect_kernel<<<1, 32>>>((const int*)dst);

    {
        int total = N_NODES * (D_FEAT / 4);
        int threads = 256;
        int blocks = (total + threads - 1) / threads;
        init_kernel<<<blocks, threads>>>(out);
    }

    {
        int threads = 256;  // 8 warps = 8 edges per block
        long long total_threads = (long long)N_EDGES * 32;
        int blocks = (int)((total_threads + threads - 1) / threads);
        scatter_kernel<<<blocks, threads>>>(emb, src, dst, out);
    }

    {
        int total = N_NODES * (D_FEAT / 4);
        int threads = 256;
        int blocks = (total + threads - 1) / threads;
        finalize_kernel<<<blocks, threads>>>(out);
    }
}

// round 3
// speedup vs baseline: 2.0243x; 2.0243x over previous
#include <cuda_runtime.h>
#include <cuda_bf16.h>
#include <cstdint>

#define N_NODES 50000
#define D_FEAT  128
#define N_EDGES 600000
#define CAP     96   // per-node bucket capacity (max in-degree ~40 for Poisson(12))

// static scratch (no cudaMalloc allowed)
__device__ int g_cnt[N_NODES];
__device__ int g_bucket[N_NODES * CAP];
__device__ int g_is64;

// ---------------------------------------------------------------------------
// Kernel 0: detect index dtype (int64 read as int32 pairs -> hi words all 0)
// ---------------------------------------------------------------------------
__global__ void detect_kernel(const int* __restrict__ idx_as_i32) {
    if (threadIdx.x == 0 && blockIdx.x == 0) {
        int is64 = 1;
        #pragma unroll 1
        for (int i = 0; i < 256; i++) {
            int lo = idx_as_i32[2 * i];
            int hi = idx_as_i32[2 * i + 1];
            if (hi != 0 || lo < 0 || lo >= N_NODES) { is64 = 0; break; }
        }
        g_is64 = is64;
    }
}

// ---------------------------------------------------------------------------
// Kernel 1: zero output (overflow-RED target) and counts
// ---------------------------------------------------------------------------
__global__ void init_kernel(float* __restrict__ out) {
    int i = blockIdx.x * blockDim.x + threadIdx.x;
    int total = N_NODES * (D_FEAT / 4);
    if (i < total) ((float4*)out)[i] = make_float4(0.f, 0.f, 0.f, 0.f);
    if (i < N_NODES) g_cnt[i] = 0;
}

// ---------------------------------------------------------------------------
// Kernel 2: bin edges by destination. One thread per edge.
// ---------------------------------------------------------------------------
__global__ void fill_kernel(const float* __restrict__ emb,
                            const void* __restrict__ src_raw,
                            const void* __restrict__ dst_raw,
                            float* __restrict__ out) {
    int e = blockIdx.x * blockDim.x + threadIdx.x;
    if (e >= N_EDGES) return;

    long long s, d;
    if (g_is64) {
        s = __ldg((const long long*)src_raw + e);
        d = __ldg((const long long*)dst_raw + e);
    } else {
        s = __ldg((const int*)src_raw + e);
        d = __ldg((const int*)dst_raw + e);
    }
    if (s < 0 || s >= N_NODES || d < 0 || d >= N_NODES) return;

    int pos = atomicAdd(&g_cnt[(int)d], 1);
    if (pos < CAP) {
        g_bucket[(int)d * CAP + pos] = (int)s;
    } else {
        // rare overflow: atomically add full row into (zeroed) output
        const float4* row = (const float4*)(emb + s * (long long)D_FEAT);
        float4* o = (float4*)(out + d * (long long)D_FEAT);
        #pragma unroll 1
        for (int i = 0; i < D_FEAT / 4; i++) {
            float4 v = __ldg(row + i);
            asm volatile("red.global.add.v4.f32 [%0], {%1, %2, %3, %4};"
                         :: "l"(o + i), "f"(v.x), "f"(v.y), "f"(v.z), "f"(v.w)
                         : "memory");
        }
    }
}

// ---------------------------------------------------------------------------
// Kernel 3: one warp per node. Gather-reduce bucketed sources, write mean once.
// ---------------------------------------------------------------------------
__global__ void agg_kernel(const float* __restrict__ emb,
                           float* __restrict__ out) {
    int gtid = blockIdx.x * blockDim.x + threadIdx.x;
    int node = gtid >> 5;
    int lane = gtid & 31;
    if (node >= N_NODES) return;

    int c = g_cnt[node];
    int m = (c < CAP) ? c : CAP;
    const int* bk = g_bucket + node * CAP;

    float4 acc = make_float4(0.f, 0.f, 0.f, 0.f);

    for (int base = 0; base < m; base += 32) {
        int lim = m - base; if (lim > 32) lim = 32;
        int s_l = (lane < lim) ? bk[base + lane] : 0;
        #pragma unroll 4
        for (int e = 0; e < lim; e++) {
            int s = __shfl_sync(0xffffffffu, s_l, e);
            float4 v = __ldg((const float4*)(emb + (long long)s * D_FEAT) + lane);
            acc.x += v.x; acc.y += v.y; acc.z += v.z; acc.w += v.w;
        }
    }

    float4* o = (float4*)out + node * (D_FEAT / 4) + lane;

    if (c > CAP) {
        // fold in the overflow contributions RED-added by fill_kernel
        float4 p = *o;
        acc.x += p.x; acc.y += p.y; acc.z += p.z; acc.w += p.w;
    }

    float inv = (c > 0) ? (1.0f / (float)c) : 0.0f;
    acc.x *= inv; acc.y *= inv; acc.z *= inv; acc.w *= inv;
    *o = acc;
}

// ---------------------------------------------------------------------------
extern "C" void kernel_launch(void* const* d_in, const int* in_sizes, int n_in,
                              void* d_out, int out_size) {
    const float* emb = (const float*)d_in[0];
    const void*  src = d_in[1];
    const void*  dst = d_in[2];
    float* out = (float*)d_out;

    detect_kernel<<<1, 32>>>((const int*)dst);

    {
        int total = N_NODES * (D_FEAT / 4);
        init_kernel<<<(total + 255) / 256, 256>>>(out);
    }
    {
        fill_kernel<<<(N_EDGES + 255) / 256, 256>>>(emb, src, dst, out);
    }
    {
        long long total_threads = (long long)N_NODES * 32;
        int blocks = (int)((total_threads + 255) / 256);
        agg_kernel<<<blocks, 256>>>(emb, out);
    }
}

// round 4
// speedup vs baseline: 2.1241x; 1.0493x over previous
#include <cuda_runtime.h>
#include <cuda_bf16.h>
#include <cstdint>

#define N_NODES 50000
#define D_FEAT  128
#define N_EDGES 600000
#define CAP     96      // per-node bucket capacity (Poisson(12) max ~40)
#define OVF_MAX 8192    // deferred overflow entries

// static scratch (no cudaMalloc allowed)
__device__ int  g_cnt[N_NODES];
__device__ int  g_bucket[N_NODES * CAP];
__device__ int  g_is64;
__device__ int  g_ovf_cnt;
__device__ int2 g_ovf[OVF_MAX];   // (dst, src)

// ---------------------------------------------------------------------------
// Kernel 1: zero counts; thread 0 of block 0 also detects index dtype.
// int64 data (values < 2^31) read as int32 pairs => (val, 0, val, 0, ...).
// ---------------------------------------------------------------------------
__global__ void init_kernel(const int* __restrict__ idx_as_i32) {
    int i = blockIdx.x * blockDim.x + threadIdx.x;
    if (i < N_NODES) g_cnt[i] = 0;
    if (i == 0) {
        g_ovf_cnt = 0;
        int is64 = 1;
        #pragma unroll 1
        for (int k = 0; k < 256; k++) {
            int lo = idx_as_i32[2 * k];
            int hi = idx_as_i32[2 * k + 1];
            if (hi != 0 || lo < 0 || lo >= N_NODES) { is64 = 0; break; }
        }
        g_is64 = is64;
    }
}

// ---------------------------------------------------------------------------
// Kernel 2: bin edges by destination. One thread per edge.
// Overflow (pos >= CAP) is pushed to a deferred list, handled post-agg.
// ---------------------------------------------------------------------------
__global__ void fill_kernel(const void* __restrict__ src_raw,
                            const void* __restrict__ dst_raw) {
    int e = blockIdx.x * blockDim.x + threadIdx.x;
    if (e >= N_EDGES) return;

    long long s, d;
    if (g_is64) {
        s = __ldg((const long long*)src_raw + e);
        d = __ldg((const long long*)dst_raw + e);
    } else {
        s = __ldg((const int*)src_raw + e);
        d = __ldg((const int*)dst_raw + e);
    }
    if (s < 0 || s >= N_NODES || d < 0 || d >= N_NODES) return;

    int pos = atomicAdd(&g_cnt[(int)d], 1);
    if (pos < CAP) {
        g_bucket[(int)d * CAP + pos] = (int)s;
    } else {
        int oi = atomicAdd(&g_ovf_cnt, 1);
        if (oi < OVF_MAX) g_ovf[oi] = make_int2((int)d, (int)s);
    }
}

// ---------------------------------------------------------------------------
// Kernel 3: one warp per node. Gather-reduce bucketed sources, write mean once.
// ---------------------------------------------------------------------------
__global__ void agg_kernel(const float* __restrict__ emb,
                           float* __restrict__ out) {
    int gtid = blockIdx.x * blockDim.x + threadIdx.x;
    int node = gtid >> 5;
    int lane = gtid & 31;
    if (node >= N_NODES) return;

    int c = g_cnt[node];
    int m = (c < CAP) ? c : CAP;
    const int* bk = g_bucket + node * CAP;

    float4 acc = make_float4(0.f, 0.f, 0.f, 0.f);

    for (int base = 0; base < m; base += 32) {
        int lim = m - base; if (lim > 32) lim = 32;
        int s_l = (lane < lim) ? bk[base + lane] : 0;
        #pragma unroll 4
        for (int e = 0; e < lim; e++) {
            int s = __shfl_sync(0xffffffffu, s_l, e);
            float4 v = __ldg((const float4*)(emb + (long long)s * D_FEAT) + lane);
            acc.x += v.x; acc.y += v.y; acc.z += v.z; acc.w += v.w;
        }
    }

    float inv = (c > 0) ? (1.0f / (float)c) : 0.0f;
    acc.x *= inv; acc.y *= inv; acc.z *= inv; acc.w *= inv;
    ((float4*)out)[node * (D_FEAT / 4) + lane] = acc;
}

// ---------------------------------------------------------------------------
// Kernel 4: fold deferred overflow edges: out[dst] += emb[src] / cnt[dst].
// One warp per overflow entry, strided over a fixed small grid.
// Empty in practice -> near-instant.
// ---------------------------------------------------------------------------
__global__ void ovf_kernel(const float* __restrict__ emb,
                           float* __restrict__ out) {
    int n = g_ovf_cnt;
    if (n > OVF_MAX) n = OVF_MAX;
    int warp = (blockIdx.x * blockDim.x + threadIdx.x) >> 5;
    int lane = threadIdx.x & 31;
    int nwarps = (gridDim.x * blockDim.x) >> 5;

    for (int i = warp; i < n; i += nwarps) {
        int2 e = g_ovf[i];
        float inv = 1.0f / (float)g_cnt[e.x];
        float4 v = __ldg((const float4*)(emb + (long long)e.y * D_FEAT) + lane);
        float4* o = (float4*)(out + (long long)e.x * D_FEAT) + lane;
        asm volatile("red.global.add.v4.f32 [%0], {%1, %2, %3, %4};"
                     :: "l"(o), "f"(v.x * inv), "f"(v.y * inv),
                        "f"(v.z * inv), "f"(v.w * inv)
                     : "memory");
    }
}

// ---------------------------------------------------------------------------
extern "C" void kernel_launch(void* const* d_in, const int* in_sizes, int n_in,
                              void* d_out, int out_size) {
    const float* emb = (const float*)d_in[0];
    const void*  src = d_in[1];
    const void*  dst = d_in[2];
    float* out = (float*)d_out;

    init_kernel<<<(N_NODES + 255) / 256, 256>>>((const int*)dst);
    fill_kernel<<<(N_EDGES + 255) / 256, 256>>>(src, dst);
    {
        long long total_threads = (long long)N_NODES * 32;
        agg_kernel<<<(int)((total_threads + 255) / 256), 256>>>(emb, out);
    }
    ovf_kernel<<<32, 256>>>(emb, out);
}